// round 5
// baseline (speedup 1.0000x reference)
#include <cuda_runtime.h>
#include <cuda_fp16.h>

#define B_  131072
#define DD  784
#define HID 256
#define MD  16
#define RS  80   // padded smem row stride (bytes) for a 32-half k-row

__device__ __align__(16) __half g_W1t_hi[HID * 832];
__device__ __align__(16) __half g_W1t_lo[HID * 832];
__device__ __align__(16) __half g_W2t_hi[HID * HID];
__device__ __align__(16) __half g_W2t_lo[HID * HID];
__device__ __align__(16) __half g_h_hi[(size_t)B_ * HID];
__device__ __align__(16) __half g_h_lo[(size_t)B_ * HID];
__device__ __align__(16) float g_xi[(size_t)B_ * MD];

__device__ __forceinline__ unsigned su32(const void* p) {
    unsigned a;
    asm("{ .reg .u64 t; cvta.to.shared.u64 t, %1; cvt.u32.u64 %0, t; }" : "=r"(a) : "l"(p));
    return a;
}
__device__ __forceinline__ void ldm4(unsigned (&r)[4], unsigned addr) {
    asm volatile("ldmatrix.sync.aligned.m8n8.x4.shared.b16 {%0,%1,%2,%3}, [%4];"
                 : "=r"(r[0]), "=r"(r[1]), "=r"(r[2]), "=r"(r[3]) : "r"(addr));
}
__device__ __forceinline__ void mma16816(float (&c)[4], const unsigned (&a)[4],
                                         unsigned b0, unsigned b1) {
    asm volatile("mma.sync.aligned.m16n8k16.row.col.f32.f16.f16.f32 "
                 "{%0,%1,%2,%3}, {%4,%5,%6,%7}, {%8,%9}, {%0,%1,%2,%3};"
                 : "+f"(c[0]), "+f"(c[1]), "+f"(c[2]), "+f"(c[3])
                 : "r"(a[0]), "r"(a[1]), "r"(a[2]), "r"(a[3]), "r"(b0), "r"(b1));
}
__device__ __forceinline__ void cpa16(unsigned s, const void* g) {
    asm volatile("cp.async.cg.shared.global [%0], [%1], 16;" :: "r"(s), "l"(g));
}
#define CP_COMMIT() asm volatile("cp.async.commit_group;" ::: "memory")
#define CP_WAIT0()  asm volatile("cp.async.wait_group 0;" ::: "memory")

__device__ __forceinline__ unsigned pk(__half a, __half b) {
    return (unsigned)__half_as_ushort(a) | ((unsigned)__half_as_ushort(b) << 16);
}
__device__ __forceinline__ void split(float v, __half& h, __half& l) {
    h = __float2half_rn(v);
    l = __float2half_rn(v - __half2float(h));
}

// prep: plain transposed row-major [n][k] fp16 hi/lo, zero-padded K for W1
__global__ void prep_kernel(const float* __restrict__ W1, const float* __restrict__ W2) {
    int idx = blockIdx.x * 256 + threadIdx.x;
    const int T1 = HID * 832;
    if (idx < T1) {
        int n = idx / 832, k = idx - n * 832;
        float v = (k < DD) ? W1[(size_t)k * HID + n] : 0.0f;
        __half h, l; split(v, h, l);
        g_W1t_hi[idx] = h; g_W1t_lo[idx] = l;
    } else if (idx < T1 + HID * HID) {
        int j = idx - T1, n = j >> 8, k = j & 255;
        float v = W2[(size_t)k * HID + n];
        __half h, l; split(v, h, l);
        g_W2t_hi[j] = h; g_W2t_lo[j] = l;
    }
}

// ------------------- GEMM1: h = relu(x@W1+b1), M64 N128 k32 ----------------
#define A1HI(s) ((s) * 10240)
#define A1LO(s) ((s) * 10240 + 5120)
#define B1HI(s) (20480 + (s) * 20480)
#define B1LO(s) (30720 + (s) * 20480)
#define SM1 61440

__global__ __launch_bounds__(256, 3)
void gemm1_k(const float* __restrict__ X, const float* __restrict__ b1v) {
    extern __shared__ char smc[];
    const unsigned sb = su32(smc);
    const int tid = threadIdx.x, lane = tid & 31, w = tid >> 5;
    const int wm = w >> 2, wn = w & 3;
    const int t8 = lane >> 3, r8 = lane & 7;
    const size_t row0 = (size_t)blockIdx.x * 64;
    const int nb = blockIdx.y;

    float acc[2][4][4] = {};
    float xr[8];
    const int ar = tid >> 2, av = tid & 3;

    auto ldgA = [&](int c) {
        int col = c * 32 + av * 8;
        if (col < DD) {
            *(float4*)xr       = *(const float4*)(X + (row0 + ar) * DD + col);
            *(float4*)(xr + 4) = *(const float4*)(X + (row0 + ar) * DD + col + 4);
        } else {
#pragma unroll
            for (int i = 0; i < 8; i++) xr[i] = 0.0f;
        }
    };
    auto stsA = [&](int s) {
        __half h[8], l[8];
#pragma unroll
        for (int i = 0; i < 8; i++) split(xr[i], h[i], l[i]);
        uint4 vh, vl;
        vh.x = pk(h[0], h[1]); vh.y = pk(h[2], h[3]); vh.z = pk(h[4], h[5]); vh.w = pk(h[6], h[7]);
        vl.x = pk(l[0], l[1]); vl.y = pk(l[2], l[3]); vl.z = pk(l[4], l[5]); vl.w = pk(l[6], l[7]);
        *(uint4*)(smc + A1HI(s) + ar * RS + av * 16) = vh;
        *(uint4*)(smc + A1LO(s) + ar * RS + av * 16) = vl;
    };
    auto cpaB = [&](int c, int s) {
#pragma unroll
        for (int i = 0; i < 2; i++) {
            int j = tid + i * 256, r = j >> 2, v = j & 3;
            const size_t src = ((size_t)(nb * 128) + r) * 832 + c * 32 + v * 8;
            cpa16(sb + B1HI(s) + r * RS + v * 16, g_W1t_hi + src);
            cpa16(sb + B1LO(s) + r * RS + v * 16, g_W1t_lo + src);
        }
    };

    ldgA(0); stsA(0); cpaB(0, 0);
    CP_COMMIT(); CP_WAIT0();
    __syncthreads();

    for (int c = 0; c < 26; c++) {
        const int s = c & 1;
        const bool more = (c + 1 < 26);
        if (more) { ldgA(c + 1); cpaB(c + 1, s ^ 1); CP_COMMIT(); }
#pragma unroll
        for (int ks = 0; ks < 2; ks++) {
            unsigned ah[2][4], al[2][4], bh[2][4], bo[2][4];
            const int u = ks * 2 + (t8 >> 1);
#pragma unroll
            for (int mi = 0; mi < 2; mi++) {
                int m = wm * 32 + mi * 16 + (t8 & 1) * 8 + r8;
                ldm4(ah[mi], sb + A1HI(s) + m * RS + u * 16);
                ldm4(al[mi], sb + A1LO(s) + m * RS + u * 16);
            }
#pragma unroll
            for (int ng = 0; ng < 2; ng++) {
                int n = wn * 32 + ng * 16 + (t8 & 1) * 8 + r8;
                ldm4(bh[ng], sb + B1HI(s) + n * RS + u * 16);
                ldm4(bo[ng], sb + B1LO(s) + n * RS + u * 16);
            }
#pragma unroll
            for (int mi = 0; mi < 2; mi++)
#pragma unroll
                for (int nj = 0; nj < 4; nj++) {
                    const int g = nj >> 1, o = nj & 1;
                    mma16816(acc[mi][nj], ah[mi], bh[g][o], bh[g][o + 2]);
                    mma16816(acc[mi][nj], ah[mi], bo[g][o], bo[g][o + 2]);
                    mma16816(acc[mi][nj], al[mi], bh[g][o], bh[g][o + 2]);
                }
        }
        if (more) stsA(s ^ 1);
        CP_WAIT0();
        __syncthreads();
    }

    const int rq = lane >> 2, cq = (lane & 3) * 2;
#pragma unroll
    for (int mi = 0; mi < 2; mi++)
#pragma unroll
        for (int nj = 0; nj < 4; nj++) {
            const int colg = nb * 128 + wn * 32 + nj * 8 + cq;
            const float bb0 = __ldg(b1v + colg), bb1 = __ldg(b1v + colg + 1);
#pragma unroll
            for (int hr = 0; hr < 2; hr++) {
                const int r = wm * 32 + mi * 16 + rq + hr * 8;
                float v0 = fmaxf(acc[mi][nj][hr * 2 + 0] + bb0, 0.0f);
                float v1 = fmaxf(acc[mi][nj][hr * 2 + 1] + bb1, 0.0f);
                __half h0, l0, h1, l1;
                split(v0, h0, l0); split(v1, h1, l1);
                const size_t gi = (row0 + r) * HID + colg;
                *(unsigned*)(g_h_hi + gi) = pk(h0, h1);
                *(unsigned*)(g_h_lo + gi) = pk(l0, l1);
            }
        }
}

// --------- GEMM2 + bias + SPD solve + Wl epilogue fused, M32 N256 k32 -------
#define A2HI(s) ((s) * 5120)
#define A2LO(s) ((s) * 5120 + 2560)
#define B2HI(s) (10240 + (s) * 40960)
#define B2LO(s) (10240 + (s) * 40960 + 20480)
#define SM2 92160

__global__ __launch_bounds__(256, 2)
void gemm2_solve_k(const float* __restrict__ b2v, const float* __restrict__ xi,
                   const float* __restrict__ t, const float* __restrict__ Wl,
                   const float* __restrict__ bl, float* __restrict__ out)
{
    extern __shared__ char smc[];
    const unsigned sb = su32(smc);
    const int tid = threadIdx.x, lane = tid & 31, w = tid >> 5;
    const int t8 = lane >> 3, r8 = lane & 7;
    const size_t row0 = (size_t)blockIdx.x * 32;

    float acc[2][4][4] = {};

    auto cpaA = [&](int c, int s) {
        const int q = tid & 127, r = q >> 2, v = q & 3;
        const size_t src = (row0 + r) * HID + c * 32 + v * 8;
        if (tid < 128) cpa16(sb + A2HI(s) + r * RS + v * 16, g_h_hi + src);
        else           cpa16(sb + A2LO(s) + r * RS + v * 16, g_h_lo + src);
    };
    auto cpaB = [&](int c, int s) {
#pragma unroll
        for (int i = 0; i < 4; i++) {
            int j = tid + i * 256, r = j >> 2, v = j & 3;
            const size_t src = (size_t)r * HID + c * 32 + v * 8;
            cpa16(sb + B2HI(s) + r * RS + v * 16, g_W2t_hi + src);
            cpa16(sb + B2LO(s) + r * RS + v * 16, g_W2t_lo + src);
        }
    };

    cpaA(0, 0); cpaB(0, 0);
    CP_COMMIT(); CP_WAIT0();
    __syncthreads();

    for (int c = 0; c < 8; c++) {
        const int s = c & 1;
        const bool more = (c + 1 < 8);
        if (more) { cpaA(c + 1, s ^ 1); cpaB(c + 1, s ^ 1); CP_COMMIT(); }
#pragma unroll
        for (int ks = 0; ks < 2; ks++) {
            unsigned ah[2][4], al[2][4], bh[2][4], bo[2][4];
            const int u = ks * 2 + (t8 >> 1);
#pragma unroll
            for (int mi = 0; mi < 2; mi++) {
                int m = mi * 16 + (t8 & 1) * 8 + r8;
                ldm4(ah[mi], sb + A2HI(s) + m * RS + u * 16);
                ldm4(al[mi], sb + A2LO(s) + m * RS + u * 16);
            }
#pragma unroll
            for (int ng = 0; ng < 2; ng++) {
                int n = w * 32 + ng * 16 + (t8 & 1) * 8 + r8;
                ldm4(bh[ng], sb + B2HI(s) + n * RS + u * 16);
                ldm4(bo[ng], sb + B2LO(s) + n * RS + u * 16);
            }
#pragma unroll
            for (int mi = 0; mi < 2; mi++)
#pragma unroll
                for (int nj = 0; nj < 4; nj++) {
                    const int g = nj >> 1, o = nj & 1;
                    mma16816(acc[mi][nj], ah[mi], bh[g][o], bh[g][o + 2]);
                    mma16816(acc[mi][nj], ah[mi], bo[g][o], bo[g][o + 2]);
                    mma16816(acc[mi][nj], al[mi], bh[g][o], bh[g][o + 2]);
                }
        }
        CP_WAIT0();
        __syncthreads();
    }

    // stage gf = acc + b2 into smem [32][264]
    float* smf = (float*)smc;
    const int rq = lane >> 2, cq = (lane & 3) * 2;
#pragma unroll
    for (int mi = 0; mi < 2; mi++)
#pragma unroll
        for (int nj = 0; nj < 4; nj++) {
            const int colg = w * 32 + nj * 8 + cq;
            const float bb0 = __ldg(b2v + colg), bb1 = __ldg(b2v + colg + 1);
#pragma unroll
            for (int hr = 0; hr < 2; hr++) {
                const int r = mi * 16 + rq + hr * 8;
                smf[r * 264 + colg]     = acc[mi][nj][hr * 2 + 0] + bb0;
                smf[r * 264 + colg + 1] = acc[mi][nj][hr * 2 + 1] + bb1;
            }
        }
    __syncthreads();

    // per-row solve: warp w handles rows w*4 .. w*4+3
    float* Gw  = smf + 8448 + w * 272;   // [16][17]
    float* Yw  = smf + 10624 + w * 16;
    float* ysm = smf + 10752;            // [32][16]
    for (int ii = 0; ii < 4; ii++) {
        const int r = w * 4 + ii;
        const float* Ar = smf + r * 264;
        for (int p = lane; p < 256; p += 32) {
            const int i = p >> 4, j = p & 15;
            float s = (i == j) ? 0.1f : 0.0f;
#pragma unroll
            for (int k = 0; k < MD; k++) s += Ar[i * 16 + k] * Ar[j * 16 + k];
            Gw[i * 17 + j] = s;
        }
        if (lane < MD)
            Yw[lane] = -__ldg(xi + (row0 + r) * MD + lane) / (__ldg(t + row0 + r) + 1e-6f);
        __syncwarp();
        for (int k = 0; k < MD; k++) {
            const float piv = Gw[k * 17 + k];
            const int i = k + 1 + lane;
            if (i < MD) {
                const float f = Gw[i * 17 + k] / piv;
                for (int c2 = k; c2 < MD; c2++) Gw[i * 17 + c2] -= f * Gw[k * 17 + c2];
                Yw[i] -= f * Yw[k];
            }
            __syncwarp();
        }
        if (lane == 0) {
            for (int k = MD - 1; k >= 0; k--) {
                float s = Yw[k];
                for (int c2 = k + 1; c2 < MD; c2++) s -= Gw[k * 17 + c2] * Yw[c2];
                Yw[k] = s / Gw[k * 17 + k];
            }
        }
        __syncwarp();
        if (lane < MD) ysm[r * MD + lane] = Yw[lane];
    }
    __syncthreads();

    // out = y @ Wl + bl for the block's 32 rows
    for (int it = 0; it < 4; it++) {
        const int col = tid + it * 256;
        if (col < DD) {
            float wv[MD];
#pragma unroll
            for (int k = 0; k < MD; k++) wv[k] = __ldg(Wl + (size_t)k * DD + col);
            const float bb = __ldg(bl + col);
            for (int r = 0; r < 32; r++) {
                float s = bb;
#pragma unroll
                for (int k = 0; k < MD; k++) s += ysm[r * MD + k] * wv[k];
                out[(row0 + r) * DD + col] = s;
            }
        }
    }
}

// xi = x @ Wp + bp
__global__ __launch_bounds__(256)
void xi_kernel(const float* __restrict__ x, const float* __restrict__ Wp,
               const float* __restrict__ bp, float* __restrict__ xo)
{
    extern __shared__ float Wps[];
    for (int i = threadIdx.x; i < DD * MD; i += 256) {
        int k = i >> 4, j = i & 15;
        Wps[j * DD + k] = Wp[i];
    }
    __syncthreads();
    const int w = threadIdx.x >> 5, lane = threadIdx.x & 31;
    for (int it = 0; it < 8; it++) {
        size_t row = (size_t)blockIdx.x * 64 + it * 8 + w;
        const float* xr = x + row * DD;
        float acc[MD];
#pragma unroll
        for (int j = 0; j < MD; j++) acc[j] = 0.0f;
        for (int k = lane; k < DD; k += 32) {
            float xv = xr[k];
#pragma unroll
            for (int j = 0; j < MD; j++) acc[j] += xv * Wps[j * DD + k];
        }
#pragma unroll
        for (int j = 0; j < MD; j++)
#pragma unroll
            for (int off = 16; off > 0; off >>= 1)
                acc[j] += __shfl_xor_sync(0xffffffffu, acc[j], off);
        if (lane < MD) xo[row * MD + lane] = acc[lane] + bp[lane];
    }
}

extern "C" void kernel_launch(void* const* d_in, const int* in_sizes, int n_in,
                              void* d_out, int out_size)
{
    const float* x_t = (const float*)d_in[0];
    const float* t   = (const float*)d_in[1];
    const float* W1  = (const float*)d_in[2];
    const float* b1  = (const float*)d_in[3];
    const float* W2  = (const float*)d_in[4];
    const float* b2  = (const float*)d_in[5];
    const float* Wp  = (const float*)d_in[6];
    const float* bp  = (const float*)d_in[7];
    const float* Wl  = (const float*)d_in[8];
    const float* bl  = (const float*)d_in[9];
    float* out = (float*)d_out;

    cudaFuncSetAttribute((const void*)gemm1_k, cudaFuncAttributeMaxDynamicSharedMemorySize, SM1);
    cudaFuncSetAttribute((const void*)gemm2_solve_k, cudaFuncAttributeMaxDynamicSharedMemorySize, SM2);
    cudaFuncSetAttribute((const void*)xi_kernel, cudaFuncAttributeMaxDynamicSharedMemorySize, DD * MD * 4);

    float* xip;
    cudaGetSymbolAddress((void**)&xip, g_xi);

    prep_kernel<<<1088, 256>>>(W1, W2);
    xi_kernel<<<B_ / 64, 256, DD * MD * 4>>>(x_t, Wp, bp, xip);
    gemm1_k<<<dim3(B_ / 64, 2), 256, SM1>>>(x_t, b1);
    gemm2_solve_k<<<B_ / 32, 256, SM2>>>(b2, xip, t, Wl, bl, out);
}

// round 6
// speedup vs baseline: 1.4269x; 1.4269x over previous
#include <cuda_runtime.h>
#include <cuda_fp16.h>

#define B_  131072
#define DD  784
#define HID 256
#define MD  16
#define RS  80   // padded smem row stride (bytes) for a 32-half k-row

__device__ __align__(16) __half g_W1t_hi[HID * 832];
__device__ __align__(16) __half g_W1t_lo[HID * 832];
__device__ __align__(16) __half g_W2t_hi[HID * HID];
__device__ __align__(16) __half g_W2t_lo[HID * HID];
__device__ __align__(16) __half g_Wpt_hi[MD * 832];
__device__ __align__(16) __half g_Wpt_lo[MD * 832];
__device__ __align__(16) __half g_h_hi[(size_t)B_ * HID];
__device__ __align__(16) __half g_h_lo[(size_t)B_ * HID];
__device__ __align__(16) float g_gf[(size_t)B_ * HID];
__device__ __align__(16) float g_xi[(size_t)B_ * MD];

__device__ __forceinline__ unsigned su32(const void* p) {
    unsigned a;
    asm("{ .reg .u64 t; cvta.to.shared.u64 t, %1; cvt.u32.u64 %0, t; }" : "=r"(a) : "l"(p));
    return a;
}
__device__ __forceinline__ void ldm4(unsigned (&r)[4], unsigned addr) {
    asm volatile("ldmatrix.sync.aligned.m8n8.x4.shared.b16 {%0,%1,%2,%3}, [%4];"
                 : "=r"(r[0]), "=r"(r[1]), "=r"(r[2]), "=r"(r[3]) : "r"(addr));
}
__device__ __forceinline__ void mma16816(float (&c)[4], const unsigned (&a)[4],
                                         unsigned b0, unsigned b1) {
    asm volatile("mma.sync.aligned.m16n8k16.row.col.f32.f16.f16.f32 "
                 "{%0,%1,%2,%3}, {%4,%5,%6,%7}, {%8,%9}, {%0,%1,%2,%3};"
                 : "+f"(c[0]), "+f"(c[1]), "+f"(c[2]), "+f"(c[3])
                 : "r"(a[0]), "r"(a[1]), "r"(a[2]), "r"(a[3]), "r"(b0), "r"(b1));
}
__device__ __forceinline__ void cpa16(unsigned s, const void* g) {
    asm volatile("cp.async.cg.shared.global [%0], [%1], 16;" :: "r"(s), "l"(g));
}
#define CP_COMMIT() asm volatile("cp.async.commit_group;" ::: "memory")
#define CP_WAIT0()  asm volatile("cp.async.wait_group 0;" ::: "memory")

__device__ __forceinline__ unsigned pk(__half a, __half b) {
    return (unsigned)__half_as_ushort(a) | ((unsigned)__half_as_ushort(b) << 16);
}
__device__ __forceinline__ void split(float v, __half& h, __half& l) {
    h = __float2half_rn(v);
    l = __float2half_rn(v - __half2float(h));
}

// prep: plain transposed row-major [n][k] fp16 hi/lo, zero-padded K
__global__ void prep_kernel(const float* __restrict__ W1, const float* __restrict__ W2,
                            const float* __restrict__ Wp) {
    int idx = blockIdx.x * 256 + threadIdx.x;
    const int T1 = HID * 832, T2 = HID * HID, T3 = MD * 832;
    if (idx < T1) {
        int n = idx / 832, k = idx - n * 832;
        float v = (k < DD) ? W1[(size_t)k * HID + n] : 0.0f;
        __half h, l; split(v, h, l);
        g_W1t_hi[idx] = h; g_W1t_lo[idx] = l;
    } else if (idx < T1 + T2) {
        int j = idx - T1, n = j >> 8, k = j & 255;
        float v = W2[(size_t)k * HID + n];
        __half h, l; split(v, h, l);
        g_W2t_hi[j] = h; g_W2t_lo[j] = l;
    } else if (idx < T1 + T2 + T3) {
        int j = idx - T1 - T2, n = j / 832, k = j - n * 832;
        float v = (k < DD) ? Wp[(size_t)k * MD + n] : 0.0f;
        __half h, l; split(v, h, l);
        g_Wpt_hi[j] = h; g_Wpt_lo[j] = l;
    }
}

// ------------------- GEMM1: h = relu(x@W1+b1) [+ fused xi], M64 N128 k32 ----
#define A1HI(s) ((s) * 10240)
#define A1LO(s) ((s) * 10240 + 5120)
#define B1HI(s) (20480 + (s) * 20480)
#define B1LO(s) (30720 + (s) * 20480)
#define P1HI(s) (61440 + (s) * 2560)
#define P1LO(s) (61440 + (s) * 2560 + 1280)
#define SM1_0 61440
#define SM1_1 66560

template <int XI>
__global__ __launch_bounds__(256, XI ? 2 : 3)
void gemm1_k(const float* __restrict__ X, const float* __restrict__ b1v,
             const float* __restrict__ bpv, int nb) {
    extern __shared__ char smc[];
    const unsigned sb = su32(smc);
    const int tid = threadIdx.x, lane = tid & 31, w = tid >> 5;
    const int wm = w >> 2, wn = w & 3;
    const int t8 = lane >> 3, r8 = lane & 7;
    const size_t row0 = (size_t)blockIdx.x * 64;

    float acc[2][4][4] = {};
    float axi[2][2][4] = {};
    float xr[8];
    const int ar = tid >> 2, av = tid & 3;

    auto ldgA = [&](int c) {
        int col = c * 32 + av * 8;
        if (col < DD) {
            *(float4*)xr       = *(const float4*)(X + (row0 + ar) * DD + col);
            *(float4*)(xr + 4) = *(const float4*)(X + (row0 + ar) * DD + col + 4);
        } else {
#pragma unroll
            for (int i = 0; i < 8; i++) xr[i] = 0.0f;
        }
    };
    auto stsA = [&](int s) {
        __half h[8], l[8];
#pragma unroll
        for (int i = 0; i < 8; i++) split(xr[i], h[i], l[i]);
        uint4 vh, vl;
        vh.x = pk(h[0], h[1]); vh.y = pk(h[2], h[3]); vh.z = pk(h[4], h[5]); vh.w = pk(h[6], h[7]);
        vl.x = pk(l[0], l[1]); vl.y = pk(l[2], l[3]); vl.z = pk(l[4], l[5]); vl.w = pk(l[6], l[7]);
        *(uint4*)(smc + A1HI(s) + ar * RS + av * 16) = vh;
        *(uint4*)(smc + A1LO(s) + ar * RS + av * 16) = vl;
    };
    auto cpaB = [&](int c, int s) {
#pragma unroll
        for (int i = 0; i < 2; i++) {
            int j = tid + i * 256, r = j >> 2, v = j & 3;
            const size_t src = ((size_t)(nb * 128) + r) * 832 + c * 32 + v * 8;
            cpa16(sb + B1HI(s) + r * RS + v * 16, g_W1t_hi + src);
            cpa16(sb + B1LO(s) + r * RS + v * 16, g_W1t_lo + src);
        }
        if (XI && tid < 128) {
            int r = (tid & 63) >> 2, v = tid & 3;
            const size_t src = (size_t)r * 832 + c * 32 + v * 8;
            if (tid < 64) cpa16(sb + P1HI(s) + r * RS + v * 16, g_Wpt_hi + src);
            else          cpa16(sb + P1LO(s) + r * RS + v * 16, g_Wpt_lo + src);
        }
    };

    ldgA(0); stsA(0); cpaB(0, 0);
    CP_COMMIT(); CP_WAIT0();
    __syncthreads();

    for (int c = 0; c < 26; c++) {
        const int s = c & 1;
        const bool more = (c + 1 < 26);
        if (more) { ldgA(c + 1); cpaB(c + 1, s ^ 1); CP_COMMIT(); }
#pragma unroll
        for (int ks = 0; ks < 2; ks++) {
            unsigned ah[2][4], al[2][4], bh[2][4], bo[2][4];
            const int u = ks * 2 + (t8 >> 1);
#pragma unroll
            for (int mi = 0; mi < 2; mi++) {
                int m = wm * 32 + mi * 16 + (t8 & 1) * 8 + r8;
                ldm4(ah[mi], sb + A1HI(s) + m * RS + u * 16);
                ldm4(al[mi], sb + A1LO(s) + m * RS + u * 16);
            }
#pragma unroll
            for (int ng = 0; ng < 2; ng++) {
                int n = wn * 32 + ng * 16 + (t8 & 1) * 8 + r8;
                ldm4(bh[ng], sb + B1HI(s) + n * RS + u * 16);
                ldm4(bo[ng], sb + B1LO(s) + n * RS + u * 16);
            }
#pragma unroll
            for (int mi = 0; mi < 2; mi++)
#pragma unroll
                for (int nj = 0; nj < 4; nj++) {
                    const int g = nj >> 1, o = nj & 1;
                    mma16816(acc[mi][nj], ah[mi], bh[g][o], bh[g][o + 2]);
                    mma16816(acc[mi][nj], ah[mi], bo[g][o], bo[g][o + 2]);
                    mma16816(acc[mi][nj], al[mi], bh[g][o], bh[g][o + 2]);
                }
            if (XI && wn == 0) {
                unsigned ph[4], po[4];
                int n = (t8 & 1) * 8 + r8;
                ldm4(ph, sb + P1HI(s) + n * RS + u * 16);
                ldm4(po, sb + P1LO(s) + n * RS + u * 16);
#pragma unroll
                for (int mi = 0; mi < 2; mi++)
#pragma unroll
                    for (int nj = 0; nj < 2; nj++) {
                        mma16816(axi[mi][nj], ah[mi], ph[nj], ph[nj + 2]);
                        mma16816(axi[mi][nj], ah[mi], po[nj], po[nj + 2]);
                        mma16816(axi[mi][nj], al[mi], ph[nj], ph[nj + 2]);
                    }
            }
        }
        if (more) stsA(s ^ 1);
        CP_WAIT0();
        __syncthreads();
    }

    const int rq = lane >> 2, cq = (lane & 3) * 2;
#pragma unroll
    for (int mi = 0; mi < 2; mi++)
#pragma unroll
        for (int nj = 0; nj < 4; nj++) {
            const int colg = nb * 128 + wn * 32 + nj * 8 + cq;
            const float bb0 = __ldg(b1v + colg), bb1 = __ldg(b1v + colg + 1);
#pragma unroll
            for (int hr = 0; hr < 2; hr++) {
                const int r = wm * 32 + mi * 16 + rq + hr * 8;
                float v0 = fmaxf(acc[mi][nj][hr * 2 + 0] + bb0, 0.0f);
                float v1 = fmaxf(acc[mi][nj][hr * 2 + 1] + bb1, 0.0f);
                __half h0, l0, h1, l1;
                split(v0, h0, l0); split(v1, h1, l1);
                const size_t gi = (row0 + r) * HID + colg;
                *(unsigned*)(g_h_hi + gi) = pk(h0, h1);
                *(unsigned*)(g_h_lo + gi) = pk(l0, l1);
            }
        }
    if (XI && wn == 0) {
#pragma unroll
        for (int mi = 0; mi < 2; mi++)
#pragma unroll
            for (int nj = 0; nj < 2; nj++) {
                const int colg = nj * 8 + cq;
                const float bb0 = __ldg(bpv + colg), bb1 = __ldg(bpv + colg + 1);
#pragma unroll
                for (int hr = 0; hr < 2; hr++) {
                    const int r = wm * 32 + mi * 16 + rq + hr * 8;
                    float2 v = make_float2(axi[mi][nj][hr * 2 + 0] + bb0,
                                           axi[mi][nj][hr * 2 + 1] + bb1);
                    *(float2*)(g_xi + (row0 + r) * MD + colg) = v;
                }
            }
    }
}

// ------------------- GEMM2: gf = h@W2+b2, M64 N128 k32 ---------------------
__global__ __launch_bounds__(256, 3)
void gemm2_k(const float* __restrict__ b2v, int nb) {
    extern __shared__ char smc[];
    const unsigned sb = su32(smc);
    const int tid = threadIdx.x, lane = tid & 31, w = tid >> 5;
    const int wm = w >> 2, wn = w & 3;
    const int t8 = lane >> 3, r8 = lane & 7;
    const size_t row0 = (size_t)blockIdx.x * 64;

    float acc[2][4][4] = {};

    auto cpaA = [&](int c, int s) {
        int r = tid >> 2, v = tid & 3;
        const size_t src = (row0 + r) * HID + c * 32 + v * 8;
        cpa16(sb + A1HI(s) + r * RS + v * 16, g_h_hi + src);
        cpa16(sb + A1LO(s) + r * RS + v * 16, g_h_lo + src);
    };
    auto cpaB = [&](int c, int s) {
#pragma unroll
        for (int i = 0; i < 2; i++) {
            int j = tid + i * 256, r = j >> 2, v = j & 3;
            const size_t src = ((size_t)(nb * 128) + r) * HID + c * 32 + v * 8;
            cpa16(sb + B1HI(s) + r * RS + v * 16, g_W2t_hi + src);
            cpa16(sb + B1LO(s) + r * RS + v * 16, g_W2t_lo + src);
        }
    };

    cpaA(0, 0); cpaB(0, 0);
    CP_COMMIT(); CP_WAIT0();
    __syncthreads();

    for (int c = 0; c < 8; c++) {
        const int s = c & 1;
        const bool more = (c + 1 < 8);
        if (more) { cpaA(c + 1, s ^ 1); cpaB(c + 1, s ^ 1); CP_COMMIT(); }
#pragma unroll
        for (int ks = 0; ks < 2; ks++) {
            unsigned ah[2][4], al[2][4], bh[2][4], bo[2][4];
            const int u = ks * 2 + (t8 >> 1);
#pragma unroll
            for (int mi = 0; mi < 2; mi++) {
                int m = wm * 32 + mi * 16 + (t8 & 1) * 8 + r8;
                ldm4(ah[mi], sb + A1HI(s) + m * RS + u * 16);
                ldm4(al[mi], sb + A1LO(s) + m * RS + u * 16);
            }
#pragma unroll
            for (int ng = 0; ng < 2; ng++) {
                int n = wn * 32 + ng * 16 + (t8 & 1) * 8 + r8;
                ldm4(bh[ng], sb + B1HI(s) + n * RS + u * 16);
                ldm4(bo[ng], sb + B1LO(s) + n * RS + u * 16);
            }
#pragma unroll
            for (int mi = 0; mi < 2; mi++)
#pragma unroll
                for (int nj = 0; nj < 4; nj++) {
                    const int g = nj >> 1, o = nj & 1;
                    mma16816(acc[mi][nj], ah[mi], bh[g][o], bh[g][o + 2]);
                    mma16816(acc[mi][nj], ah[mi], bo[g][o], bo[g][o + 2]);
                    mma16816(acc[mi][nj], al[mi], bh[g][o], bh[g][o + 2]);
                }
        }
        CP_WAIT0();
        __syncthreads();
    }

    const int rq = lane >> 2, cq = (lane & 3) * 2;
#pragma unroll
    for (int mi = 0; mi < 2; mi++)
#pragma unroll
        for (int nj = 0; nj < 4; nj++) {
            const int colg = nb * 128 + wn * 32 + nj * 8 + cq;
            const float bb0 = __ldg(b2v + colg), bb1 = __ldg(b2v + colg + 1);
#pragma unroll
            for (int hr = 0; hr < 2; hr++) {
                const int r = wm * 32 + mi * 16 + rq + hr * 8;
                float2 v = make_float2(acc[mi][nj][hr * 2 + 0] + bb0,
                                       acc[mi][nj][hr * 2 + 1] + bb1);
                *(float2*)(g_gf + (row0 + r) * HID + colg) = v;
            }
        }
}

// ---------- solve: 32 rows/block, warp-per-row SPD solve + Wl epilogue ------
__global__ __launch_bounds__(256)
void solve_k(const float* __restrict__ t, const float* __restrict__ Wl,
             const float* __restrict__ bl, float* __restrict__ out)
{
    __shared__ float Asm[8][16 * 17];
    __shared__ float Gsm[8][16 * 17];
    __shared__ float ysm[32][MD];
    const int tid = threadIdx.x, w = tid >> 5, lane = tid & 31;
    const size_t row0 = (size_t)blockIdx.x * 32;

    for (int ii = 0; ii < 4; ii++) {
        const int r = w * 4 + ii;
        const size_t grow = row0 + r;
        const float* gfr = g_gf + grow * HID;
        for (int p = lane; p < 256; p += 32) Asm[w][(p >> 4) * 17 + (p & 15)] = gfr[p];
        if (lane < MD)
            ysm[r][lane] = -__ldg(g_xi + grow * MD + lane) / (__ldg(t + grow) + 1e-6f);
        __syncwarp();
        for (int p = lane; p < 256; p += 32) {
            const int i = p >> 4, j = p & 15;
            float s = (i == j) ? 0.1f : 0.0f;
#pragma unroll
            for (int k = 0; k < MD; k++) s += Asm[w][i * 17 + k] * Asm[w][j * 17 + k];
            Gsm[w][i * 17 + j] = s;
        }
        __syncwarp();
        for (int k = 0; k < MD; k++) {
            const float piv = Gsm[w][k * 17 + k];
            const int i = k + 1 + lane;
            if (i < MD) {
                const float f = Gsm[w][i * 17 + k] / piv;
                for (int c2 = k; c2 < MD; c2++) Gsm[w][i * 17 + c2] -= f * Gsm[w][k * 17 + c2];
                ysm[r][i] -= f * ysm[r][k];
            }
            __syncwarp();
        }
        if (lane == 0) {
            for (int k = MD - 1; k >= 0; k--) {
                float s = ysm[r][k];
                for (int c2 = k + 1; c2 < MD; c2++) s -= Gsm[w][k * 17 + c2] * ysm[r][c2];
                ysm[r][k] = s / Gsm[w][k * 17 + k];
            }
        }
        __syncwarp();
    }
    __syncthreads();

    for (int it = 0; it < 4; it++) {
        const int col = tid + it * 256;
        if (col < DD) {
            float wv[MD];
#pragma unroll
            for (int k = 0; k < MD; k++) wv[k] = __ldg(Wl + (size_t)k * DD + col);
            const float bb = __ldg(bl + col);
            for (int r2 = 0; r2 < 32; r2++) {
                float s = bb;
#pragma unroll
                for (int k = 0; k < MD; k++) s += ysm[r2][k] * wv[k];
                out[(row0 + r2) * DD + col] = s;
            }
        }
    }
}

extern "C" void kernel_launch(void* const* d_in, const int* in_sizes, int n_in,
                              void* d_out, int out_size)
{
    const float* x_t = (const float*)d_in[0];
    const float* t   = (const float*)d_in[1];
    const float* W1  = (const float*)d_in[2];
    const float* b1  = (const float*)d_in[3];
    const float* W2  = (const float*)d_in[4];
    const float* b2  = (const float*)d_in[5];
    const float* Wp  = (const float*)d_in[6];
    const float* bp  = (const float*)d_in[7];
    const float* Wl  = (const float*)d_in[8];
    const float* bl  = (const float*)d_in[9];
    float* out = (float*)d_out;

    cudaFuncSetAttribute((const void*)gemm1_k<1>, cudaFuncAttributeMaxDynamicSharedMemorySize, SM1_1);
    cudaFuncSetAttribute((const void*)gemm1_k<0>, cudaFuncAttributeMaxDynamicSharedMemorySize, SM1_0);
    cudaFuncSetAttribute((const void*)gemm2_k,    cudaFuncAttributeMaxDynamicSharedMemorySize, SM1_0);

    prep_kernel<<<1140, 256>>>(W1, W2, Wp);
    gemm1_k<1><<<B_ / 64, 256, SM1_1>>>(x_t, b1, bp, 0);
    gemm1_k<0><<<B_ / 64, 256, SM1_0>>>(x_t, b1, bp, 1);
    gemm2_k<<<B_ / 64, 256, SM1_0>>>(b2, 0);
    gemm2_k<<<B_ / 64, 256, SM1_0>>>(b2, 1);
    solve_k<<<B_ / 32, 256>>>(t, Wl, bl, out);
}